// round 1
// baseline (speedup 1.0000x reference)
#include <cuda_runtime.h>
#include <math.h>

#define NPTS 240000
#define MPTS 60000
#define MB   16
#define NBLK (MPTS/MB)      // 3750
#define TPB  256
#define DIN  35

// ---------------- scratch (static device globals; no runtime alloc) -------
__device__ float  g_Mx[MPTS*192];     // per-m per-branch-channel max of h
__device__ float  g_Mn[MPTS*192];     // min of h
__device__ float  g_zbuf[MPTS*64];    // z = y_cat @ w + b
__device__ double g_bsum[384];        // [sum(192) | sumsq(192)] branch stats
__device__ double g_fsum[128];        // [sum(64)  | sumsq(64)]  final stats
__device__ float  g_aff1[384];        // [a(192) | c(192)]
__device__ float  g_aff2[128];        // [a(64)  | c(64)]

// ---------------- kernel 0: zero the stat accumulators --------------------
__global__ void k_init()
{
    int i = threadIdx.x;
    if (i < 384) g_bsum[i] = 0.0;
    if (i < 128) g_fsum[i] = 0.0;
}

// ---------------- branch compute helper ------------------------------------
// Computes h[j,o] = sum_c feat[c][j] * w[c][o] for j<KMAX and the thread's 4
// output channels; tracks max/min per channel and accumulates sum/sumsq.
template<int KMAX>
__device__ __forceinline__ void do_branch(const float* __restrict__ fbase,
                                          const float* __restrict__ wb,
                                          float* __restrict__ mx,
                                          float* __restrict__ mn,
                                          float* __restrict__ sm,
                                          float* __restrict__ sq)
{
    const int NT = (KMAX + 3) >> 2;
#pragma unroll
    for (int oo = 0; oo < 4; oo++) {
        mx[oo] = -3.0e38f; mn[oo] = 3.0e38f; sm[oo] = 0.f; sq[oo] = 0.f;
    }
#pragma unroll 1
    for (int jt = 0; jt < NT; jt++) {
        const int j0 = jt * 4;
        float acc[4][4];
#pragma unroll
        for (int jj = 0; jj < 4; jj++)
#pragma unroll
            for (int oo = 0; oo < 4; oo++) acc[jj][oo] = 0.f;

#pragma unroll
        for (int c = 0; c < DIN; c++) {
            const float4 f4 = *reinterpret_cast<const float4*>(fbase + c*40 + j0);
            const float4 w4 = *reinterpret_cast<const float4*>(wb + c*64);
            const float fj[4] = {f4.x, f4.y, f4.z, f4.w};
            const float wv[4] = {w4.x, w4.y, w4.z, w4.w};
#pragma unroll
            for (int jj = 0; jj < 4; jj++)
#pragma unroll
                for (int oo = 0; oo < 4; oo++)
                    acc[jj][oo] = fmaf(fj[jj], wv[oo], acc[jj][oo]);
        }
#pragma unroll
        for (int jj = 0; jj < 4; jj++) {
            if ((KMAX & 3) == 0 || (j0 + jj) < KMAX) {
#pragma unroll
                for (int oo = 0; oo < 4; oo++) {
                    const float h = acc[jj][oo];
                    mx[oo] = fmaxf(mx[oo], h);
                    mn[oo] = fminf(mn[oo], h);
                    sm[oo] += h;
                    sq[oo] = fmaf(h, h, sq[oo]);
                }
            }
        }
    }
}

// ---------------- kernel 1: gather + 3 branch GEMMs + max/min + stats -----
__global__ void __launch_bounds__(TPB) k_main(
    const float* __restrict__ p, const float* __restrict__ x,
    const int* __restrict__ fps_idx, const int* __restrict__ knn_idx,
    const float* __restrict__ w1, const float* __restrict__ w2,
    const float* __restrict__ w3, float* __restrict__ out_np)
{
    extern __shared__ float smem[];
    float* sw    = smem;                  // 3*35*64 = 6720
    float* sfeat = sw + 6720;             // MB*35*40 = 22400 (layout [m][c][j])
    float* scen  = sfeat + 22400;         // MB*4
    float* sred  = scen + 64;             // 384

    const int t  = threadIdx.x;
    const int mb = blockIdx.x * MB;

    // stage the three 35x64 weight matrices
    for (int i = t; i < 3*DIN*64; i += TPB) {
        const int b = i / (DIN*64);
        const int r = i - b*(DIN*64);
        const float* ws = (b == 0) ? w1 : ((b == 1) ? w2 : w3);
        sw[i] = ws[r];
    }
    // centroids
    if (t < MB) {
        const int fi = fps_idx[mb + t];
        scen[t*4+0] = p[fi*3+0];
        scen[t*4+1] = p[fi*3+1];
        scen[t*4+2] = p[fi*3+2];
    }
    for (int i = t; i < 384; i += TPB) sred[i] = 0.f;
    __syncthreads();

    // n_p output
    if (t < MB*3) {
        const int ml = t / 3, comp = t - ml*3;
        out_np[(mb + ml)*3 + comp] = scen[ml*4 + comp];
    }

    // stage neighbor features, transposed [c][j]
    for (int s = t; s < MB*40; s += TPB) {
        const int ml = s / 40, j = s - ml*40;
        const int idx = knn_idx[(mb + ml)*40 + j];
        float* f = sfeat + ml*1400 + j;
        f[0]  = p[idx*3+0] - scen[ml*4+0];
        f[40] = p[idx*3+1] - scen[ml*4+1];
        f[80] = p[idx*3+2] - scen[ml*4+2];
        const float4* xr = reinterpret_cast<const float4*>(x + (size_t)idx*32);
#pragma unroll
        for (int q = 0; q < 8; q++) {
            const float4 v = xr[q];
            f[(3 + 4*q + 0)*40] = v.x;
            f[(3 + 4*q + 1)*40] = v.y;
            f[(3 + 4*q + 2)*40] = v.z;
            f[(3 + 4*q + 3)*40] = v.w;
        }
    }
    __syncthreads();

    const int ml = t >> 4;          // m within block
    const int og = t & 15;          // output group
    const int o0 = og * 4;
    const int m  = mb + ml;
    const float* fbase = sfeat + ml*1400;

    float mx[4], mn[4], sm[4], sq[4];

    // branch 1 (k=10)
    do_branch<10>(fbase, sw + 0*2240 + o0, mx, mn, sm, sq);
    *reinterpret_cast<float4*>(&g_Mx[(size_t)m*192 + 0 + o0])  = make_float4(mx[0],mx[1],mx[2],mx[3]);
    *reinterpret_cast<float4*>(&g_Mn[(size_t)m*192 + 0 + o0])  = make_float4(mn[0],mn[1],mn[2],mn[3]);
#pragma unroll
    for (int oo = 0; oo < 4; oo++) {
        atomicAdd(&sred[0 + o0 + oo], sm[oo]);
        atomicAdd(&sred[192 + 0 + o0 + oo], sq[oo]);
    }
    // branch 2 (k=20)
    do_branch<20>(fbase, sw + 1*2240 + o0, mx, mn, sm, sq);
    *reinterpret_cast<float4*>(&g_Mx[(size_t)m*192 + 64 + o0]) = make_float4(mx[0],mx[1],mx[2],mx[3]);
    *reinterpret_cast<float4*>(&g_Mn[(size_t)m*192 + 64 + o0]) = make_float4(mn[0],mn[1],mn[2],mn[3]);
#pragma unroll
    for (int oo = 0; oo < 4; oo++) {
        atomicAdd(&sred[64 + o0 + oo], sm[oo]);
        atomicAdd(&sred[192 + 64 + o0 + oo], sq[oo]);
    }
    // branch 3 (k=40)
    do_branch<40>(fbase, sw + 2*2240 + o0, mx, mn, sm, sq);
    *reinterpret_cast<float4*>(&g_Mx[(size_t)m*192 + 128 + o0]) = make_float4(mx[0],mx[1],mx[2],mx[3]);
    *reinterpret_cast<float4*>(&g_Mn[(size_t)m*192 + 128 + o0]) = make_float4(mn[0],mn[1],mn[2],mn[3]);
#pragma unroll
    for (int oo = 0; oo < 4; oo++) {
        atomicAdd(&sred[128 + o0 + oo], sm[oo]);
        atomicAdd(&sred[192 + 128 + o0 + oo], sq[oo]);
    }

    __syncthreads();
    for (int i = t; i < 384; i += TPB)
        atomicAdd(&g_bsum[i], (double)sred[i]);
}

// ---------------- kernel 2: branch BN affine params -----------------------
__global__ void k_stats1(const float* __restrict__ g1, const float* __restrict__ g2,
                         const float* __restrict__ g3, const float* __restrict__ be1,
                         const float* __restrict__ be2, const float* __restrict__ be3)
{
    const int i = threadIdx.x;
    if (i >= 192) return;
    const int b = i / 64, o = i - b*64;
    const double cnt = (double)MPTS * ((b == 0) ? 10.0 : ((b == 1) ? 20.0 : 40.0));
    const double mu  = g_bsum[i] / cnt;
    const double var = g_bsum[192 + i] / cnt - mu*mu;
    const float gam = ((b == 0) ? g1 : ((b == 1) ? g2 : g3))[o];
    const float bet = ((b == 0) ? be1 : ((b == 1) ? be2 : be3))[o];
    const double a = (double)gam / sqrt(var + 1e-5);
    g_aff1[i]       = (float)a;
    g_aff1[192 + i] = (float)((double)bet - mu*a);
}

// ---------------- kernel 3: BN+relu on max/min, 192->64 GEMM, final stats -
__global__ void __launch_bounds__(TPB) k_gemm2(const float* __restrict__ w,
                                               const float* __restrict__ bias)
{
    extern __shared__ float smem[];
    float* sw   = smem;            // 192*64 = 12288
    float* sy   = sw + 12288;      // MB*192 = 3072
    float* saff = sy + 3072;       // 384
    float* sred = saff + 384;      // 128

    const int t  = threadIdx.x;
    const int mb = blockIdx.x * MB;

    for (int i = t; i < 12288; i += TPB) sw[i] = w[i];
    for (int i = t; i < 384;   i += TPB) saff[i] = g_aff1[i];
    for (int i = t; i < 128;   i += TPB) sred[i] = 0.f;
    __syncthreads();

    const int ml = t >> 4;
    const int og = t & 15;
    const int m  = mb + ml;

    // y_cat = relu(a * (a>=0 ? max : min) + c)
#pragma unroll
    for (int qq = 0; qq < 12; qq++) {
        const int q = og*12 + qq;
        const float a = saff[q], c = saff[192 + q];
        const float v = (a >= 0.f) ? g_Mx[(size_t)m*192 + q] : g_Mn[(size_t)m*192 + q];
        sy[ml*192 + q] = fmaxf(fmaf(a, v, c), 0.f);
    }
    __syncthreads();

    const int o0 = og * 4;
    float acc[4] = {bias[o0+0], bias[o0+1], bias[o0+2], bias[o0+3]};
    const float* yb = sy + ml*192;
#pragma unroll 8
    for (int q = 0; q < 192; q++) {
        const float yv = yb[q];
        const float4 w4 = *reinterpret_cast<const float4*>(sw + q*64 + o0);
        acc[0] = fmaf(yv, w4.x, acc[0]);
        acc[1] = fmaf(yv, w4.y, acc[1]);
        acc[2] = fmaf(yv, w4.z, acc[2]);
        acc[3] = fmaf(yv, w4.w, acc[3]);
    }
    *reinterpret_cast<float4*>(&g_zbuf[(size_t)m*64 + o0]) =
        make_float4(acc[0], acc[1], acc[2], acc[3]);
#pragma unroll
    for (int oo = 0; oo < 4; oo++) {
        atomicAdd(&sred[o0 + oo], acc[oo]);
        atomicAdd(&sred[64 + o0 + oo], acc[oo]*acc[oo]);
    }
    __syncthreads();
    for (int i = t; i < 128; i += TPB)
        atomicAdd(&g_fsum[i], (double)sred[i]);
}

// ---------------- kernel 4: final BN affine params ------------------------
__global__ void k_stats2(const float* __restrict__ g, const float* __restrict__ be)
{
    const int o = threadIdx.x;
    if (o >= 64) return;
    const double cnt = (double)MPTS;
    const double mu  = g_fsum[o] / cnt;
    const double var = g_fsum[64 + o] / cnt - mu*mu;
    const double a = (double)g[o] / sqrt(var + 1e-5);
    g_aff2[o]      = (float)a;
    g_aff2[64 + o] = (float)((double)be[o] - mu*a);
}

// ---------------- kernel 5: final elementwise BN+relu + n_o ---------------
__global__ void k_final(float* __restrict__ out_y, float* __restrict__ out_no)
{
    const int i = blockIdx.x * blockDim.x + threadIdx.x;  // float4 groups
    if (i < MPTS*16) {
        const int o0 = (i & 15) * 4;
        const float4 z = *reinterpret_cast<const float4*>(&g_zbuf[(size_t)i*4]);
        float4 r;
        r.x = fmaxf(fmaf(g_aff2[o0+0], z.x, g_aff2[64+o0+0]), 0.f);
        r.y = fmaxf(fmaf(g_aff2[o0+1], z.y, g_aff2[64+o0+1]), 0.f);
        r.z = fmaxf(fmaf(g_aff2[o0+2], z.z, g_aff2[64+o0+2]), 0.f);
        r.w = fmaxf(fmaf(g_aff2[o0+3], z.w, g_aff2[64+o0+3]), 0.f);
        *reinterpret_cast<float4*>(&out_y[(size_t)i*4]) = r;
    }
    if (i == 0) out_no[0] = (float)MPTS;
}

// ---------------- launch ---------------------------------------------------
extern "C" void kernel_launch(void* const* d_in, const int* in_sizes, int n_in,
                              void* d_out, int out_size)
{
    const float* p   = (const float*)d_in[0];
    const float* x   = (const float*)d_in[1];
    const int*   fps = (const int*)  d_in[3];
    const int*   knn = (const int*)  d_in[4];
    const float* w1  = (const float*)d_in[5];
    const float* w2  = (const float*)d_in[6];
    const float* w3  = (const float*)d_in[7];
    const float* w   = (const float*)d_in[8];
    const float* b   = (const float*)d_in[9];
    const float* g1  = (const float*)d_in[10];
    const float* g2  = (const float*)d_in[11];
    const float* g3  = (const float*)d_in[12];
    const float* g   = (const float*)d_in[13];
    const float* be1 = (const float*)d_in[14];
    const float* be2 = (const float*)d_in[15];
    const float* be3 = (const float*)d_in[16];
    const float* be  = (const float*)d_in[17];

    float* out    = (float*)d_out;
    float* out_np = out;                       // [M,3]
    float* out_y  = out + (size_t)MPTS*3;      // [M,64]
    float* out_no = out + (size_t)MPTS*3 + (size_t)MPTS*64;  // [1]

    const int smem1 = (6720 + 22400 + 64 + 384) * 4;          // 118272
    const int smem3 = (12288 + 3072 + 384 + 128) * 4;         // 63488
    cudaFuncSetAttribute(k_main,  cudaFuncAttributeMaxDynamicSharedMemorySize, smem1);
    cudaFuncSetAttribute(k_gemm2, cudaFuncAttributeMaxDynamicSharedMemorySize, smem3);

    k_init<<<1, 512>>>();
    k_main<<<NBLK, TPB, smem1>>>(p, x, fps, knn, w1, w2, w3, out_np);
    k_stats1<<<1, 192>>>(g1, g2, g3, be1, be2, be3);
    k_gemm2<<<NBLK, TPB, smem3>>>(w, b);
    k_stats2<<<1, 64>>>(g, be);
    k_final<<<3750, 256>>>(out_y, out_no);
}

// round 3
// speedup vs baseline: 1.2736x; 1.2736x over previous
#include <cuda_runtime.h>
#include <math.h>

#define NPTS 240000
#define MPTS 60000
#define TPB  256

// ---------------- scratch (static device globals; no runtime alloc) -------
__device__ float  g_P[(size_t)NPTS*192];   // x-part of branch GEMMs, per point
__device__ float  g_Mx[(size_t)MPTS*192];  // per-m per-branch-channel max of h
__device__ float  g_Mn[(size_t)MPTS*192];  // min of h
__device__ float  g_zbuf[(size_t)MPTS*64]; // z = y_cat @ w + b
__device__ double g_bsum[384];             // [sum(192) | sumsq(192)] branch stats
__device__ double g_fsum[128];             // [sum(64)  | sumsq(64)]  final stats
__device__ float  g_aff1[384];             // [a(192) | c(192)]
__device__ float  g_aff2[128];             // [a(64)  | c(64)]

// ---------------- f32x2 helpers -------------------------------------------
__device__ __forceinline__ void fma2(unsigned long long &d,
                                     unsigned long long a, unsigned long long b)
{
    asm("fma.rn.f32x2 %0, %1, %2, %0;" : "+l"(d) : "l"(a), "l"(b));
}
__device__ __forceinline__ unsigned long long pack2(float lo, float hi)
{
    unsigned long long r;
    asm("mov.b64 %0, {%1, %2};" : "=l"(r) : "f"(lo), "f"(hi));
    return r;
}
__device__ __forceinline__ float2 unpack2(unsigned long long v)
{
    float2 r;
    asm("mov.b64 {%0, %1}, %2;" : "=f"(r.x), "=f"(r.y) : "l"(v));
    return r;
}

// ---------------- kernel 0: zero the stat accumulators --------------------
__global__ void k_init()
{
    int i = threadIdx.x;
    if (i < 384) g_bsum[i] = 0.0;
    if (i < 128) g_fsum[i] = 0.0;
}

// ---------------- kernel A: P[n,192] = x[n,:32] @ [w1|w2|w3][3:35,:] ------
// NB=128 points per block (240000 = 128*1875, exact).
// threads: og = t&7 (8 o-groups of 8), ng = t>>3 (32 n-groups of 4).
// FFMA2: pack over o (w pairs natural), x duplicated in smem.
__global__ void __launch_bounds__(TPB) k_pgemm(
    const float* __restrict__ x,
    const float* __restrict__ w1, const float* __restrict__ w2,
    const float* __restrict__ w3)
{
    extern __shared__ float smem[];
    float2* sxd = reinterpret_cast<float2*>(smem);  // [32 c][128 n] dup pairs (32KB)
    float*  sw  = smem + 8192;                      // [3][32 c][64 o]        (24KB)

    const int t  = threadIdx.x;
    const int n0 = blockIdx.x * 128;

    // stage weight rows 3..34 (the x-part)
    for (int i = t; i < 6144; i += TPB) {
        const int b = i >> 11;
        const int r = i & 2047;
        const int c = r >> 6, o = r & 63;
        const float* ws = (b == 0) ? w1 : ((b == 1) ? w2 : w3);
        sw[i] = ws[(3 + c)*64 + o];
    }
    // stage x duplicated: i = (nl, c4)
    for (int i = t; i < 1024; i += TPB) {
        const int nl = i >> 3, c4 = i & 7;
        const float4 v = *reinterpret_cast<const float4*>(
            x + (size_t)(n0 + nl)*32 + c4*4);
        sxd[(c4*4 + 0)*128 + nl] = make_float2(v.x, v.x);
        sxd[(c4*4 + 1)*128 + nl] = make_float2(v.y, v.y);
        sxd[(c4*4 + 2)*128 + nl] = make_float2(v.z, v.z);
        sxd[(c4*4 + 3)*128 + nl] = make_float2(v.w, v.w);
    }
    __syncthreads();

    const int og = t & 7, ng = t >> 3;
    const int nb = ng * 4;      // 4 n per thread
    const int o0 = og * 8;      // 8 o per thread

#pragma unroll 1
    for (int b = 0; b < 3; b++) {
        unsigned long long acc[4][4];
#pragma unroll
        for (int i = 0; i < 4; i++)
#pragma unroll
            for (int j = 0; j < 4; j++) acc[i][j] = 0ULL;

        const float* wb = sw + b*2048 + o0;
#pragma unroll
        for (int c = 0; c < 32; c++) {
            const ulonglong2* xp =
                reinterpret_cast<const ulonglong2*>(sxd + c*128 + nb);
            const ulonglong2 xa = xp[0];
            const ulonglong2 xb = xp[1];
            const ulonglong2* wp =
                reinterpret_cast<const ulonglong2*>(wb + c*64);
            const ulonglong2 wv = wp[0];
            const ulonglong2 wv2 = wp[1];
            const unsigned long long xv[4] = {xa.x, xa.y, xb.x, xb.y};
            const unsigned long long wr[4] = {wv.x, wv.y, wv2.x, wv2.y};
#pragma unroll
            for (int i = 0; i < 4; i++)
#pragma unroll
                for (int j = 0; j < 4; j++) fma2(acc[i][j], xv[i], wr[j]);
        }
#pragma unroll
        for (int i = 0; i < 4; i++) {
            const int n = n0 + nb + i;
            const float2 a0 = unpack2(acc[i][0]), a1 = unpack2(acc[i][1]);
            const float2 a2 = unpack2(acc[i][2]), a3 = unpack2(acc[i][3]);
            float* dst = g_P + (size_t)n*192 + b*64 + o0;
            *reinterpret_cast<float4*>(dst)     = make_float4(a0.x, a0.y, a1.x, a1.y);
            *reinterpret_cast<float4*>(dst + 4) = make_float4(a2.x, a2.y, a3.x, a3.y);
        }
    }
}

// ---------------- kernel B: gather P + rel part + max/min + stats ---------
// MB=16 m per block (3750 blocks). thread = (ml = t>>4, og = t&15, o-tile 4)
__global__ void __launch_bounds__(TPB) k_comb(
    const float* __restrict__ p,
    const int* __restrict__ fps_idx, const int* __restrict__ knn_idx,
    const float* __restrict__ w1, const float* __restrict__ w2,
    const float* __restrict__ w3, float* __restrict__ out_np)
{
    __shared__ float4 srel[16*40];   // rel.xyz + idx byte-offset
    __shared__ float  swx[576];      // [3 b][3 c][64 o] xyz weight rows
    __shared__ float  scen[16*4];
    __shared__ float  sred[384];

    const int t  = threadIdx.x;
    const int mb = blockIdx.x * 16;

    if (t < 16) {
        const int fi = fps_idx[mb + t];
        scen[t*4+0] = p[fi*3+0];
        scen[t*4+1] = p[fi*3+1];
        scen[t*4+2] = p[fi*3+2];
    }
    for (int i = t; i < 576; i += TPB) {
        const int b = i / 192, r = i - b*192;   // r = c*64+o, c<3
        const float* ws = (b == 0) ? w1 : ((b == 1) ? w2 : w3);
        swx[i] = ws[r];
    }
    for (int i = t; i < 384; i += TPB) sred[i] = 0.f;
    __syncthreads();

    if (t < 48) {
        const int ml = t / 3, comp = t - ml*3;
        out_np[(mb + ml)*3 + comp] = scen[ml*4 + comp];
    }

    // stage rel + P byte offsets
    for (int s = t; s < 640; s += TPB) {
        const int ml = s / 40, j = s - ml*40;
        const int idx = knn_idx[(mb + ml)*40 + j];
        float4 r;
        r.x = p[idx*3+0] - scen[ml*4+0];
        r.y = p[idx*3+1] - scen[ml*4+1];
        r.z = p[idx*3+2] - scen[ml*4+2];
        r.w = __int_as_float(idx * 768);
        srel[s] = r;
    }
    __syncthreads();

    const int ml = t >> 4, og = t & 15, o0 = og * 4;
    const int m  = mb + ml;
    const char* Pbase = reinterpret_cast<const char*>(g_P);

#pragma unroll
    for (int b = 0; b < 3; b++) {
        const int KB = (b == 0) ? 10 : ((b == 1) ? 20 : 40);
        const float4 wx = *reinterpret_cast<const float4*>(&swx[b*192 +   0 + o0]);
        const float4 wy = *reinterpret_cast<const float4*>(&swx[b*192 +  64 + o0]);
        const float4 wz = *reinterpret_cast<const float4*>(&swx[b*192 + 128 + o0]);

        float mx0=-3e38f, mx1=-3e38f, mx2=-3e38f, mx3=-3e38f;
        float mn0= 3e38f, mn1= 3e38f, mn2= 3e38f, mn3= 3e38f;
        float sm0=0.f, sm1=0.f, sm2=0.f, sm3=0.f;
        float sq0=0.f, sq1=0.f, sq2=0.f, sq3=0.f;

#pragma unroll 2
        for (int j = 0; j < KB; j++) {
            const float4 r = srel[ml*40 + j];
            const int off = __float_as_int(r.w) + b*256 + o0*4;  // FIXED: bytes = floats*4
            const float4 P4 = *reinterpret_cast<const float4*>(Pbase + off);
            float h0 = fmaf(r.x, wx.x, P4.x);
            float h1 = fmaf(r.x, wx.y, P4.y);
            float h2 = fmaf(r.x, wx.z, P4.z);
            float h3 = fmaf(r.x, wx.w, P4.w);
            h0 = fmaf(r.y, wy.x, h0); h1 = fmaf(r.y, wy.y, h1);
            h2 = fmaf(r.y, wy.z, h2); h3 = fmaf(r.y, wy.w, h3);
            h0 = fmaf(r.z, wz.x, h0); h1 = fmaf(r.z, wz.y, h1);
            h2 = fmaf(r.z, wz.z, h2); h3 = fmaf(r.z, wz.w, h3);
            mx0 = fmaxf(mx0, h0); mx1 = fmaxf(mx1, h1);
            mx2 = fmaxf(mx2, h2); mx3 = fmaxf(mx3, h3);
            mn0 = fminf(mn0, h0); mn1 = fminf(mn1, h1);
            mn2 = fminf(mn2, h2); mn3 = fminf(mn3, h3);
            sm0 += h0; sm1 += h1; sm2 += h2; sm3 += h3;
            sq0 = fmaf(h0, h0, sq0); sq1 = fmaf(h1, h1, sq1);
            sq2 = fmaf(h2, h2, sq2); sq3 = fmaf(h3, h3, sq3);
        }
        *reinterpret_cast<float4*>(&g_Mx[(size_t)m*192 + b*64 + o0]) =
            make_float4(mx0, mx1, mx2, mx3);
        *reinterpret_cast<float4*>(&g_Mn[(size_t)m*192 + b*64 + o0]) =
            make_float4(mn0, mn1, mn2, mn3);
        atomicAdd(&sred[b*64 + o0 + 0], sm0);
        atomicAdd(&sred[b*64 + o0 + 1], sm1);
        atomicAdd(&sred[b*64 + o0 + 2], sm2);
        atomicAdd(&sred[b*64 + o0 + 3], sm3);
        atomicAdd(&sred[192 + b*64 + o0 + 0], sq0);
        atomicAdd(&sred[192 + b*64 + o0 + 1], sq1);
        atomicAdd(&sred[192 + b*64 + o0 + 2], sq2);
        atomicAdd(&sred[192 + b*64 + o0 + 3], sq3);
    }
    __syncthreads();
    for (int i = t; i < 384; i += TPB)
        atomicAdd(&g_bsum[i], (double)sred[i]);
}

// ---------------- kernel 2: branch BN affine params -----------------------
__global__ void k_stats1(const float* __restrict__ g1, const float* __restrict__ g2,
                         const float* __restrict__ g3, const float* __restrict__ be1,
                         const float* __restrict__ be2, const float* __restrict__ be3)
{
    const int i = threadIdx.x;
    if (i >= 192) return;
    const int b = i / 64, o = i - b*64;
    const double cnt = (double)MPTS * ((b == 0) ? 10.0 : ((b == 1) ? 20.0 : 40.0));
    const double mu  = g_bsum[i] / cnt;
    const double var = g_bsum[192 + i] / cnt - mu*mu;
    const float gam = ((b == 0) ? g1 : ((b == 1) ? g2 : g3))[o];
    const float bet = ((b == 0) ? be1 : ((b == 1) ? be2 : be3))[o];
    const double a = (double)gam / sqrt(var + 1e-5);
    g_aff1[i]       = (float)a;
    g_aff1[192 + i] = (float)((double)bet - mu*a);
}

// ---------------- kernel 3: BN+relu on max/min, 192->64 GEMM, final stats -
// MB=64 m per block (938 blocks, guarded). FFMA2: pack over o; y dup'd on fly.
__global__ void __launch_bounds__(TPB) k_gemm2(const float* __restrict__ w,
                                               const float* __restrict__ bias)
{
    extern __shared__ float smem[];
    float* sw   = smem;               // 12288  [192 q][64 o]
    float* sy   = sw + 12288;         // 12672  [192 q][66] (pad 2, m fastest)
    float* saff = sy + 12672;         // 384
    float* sred = saff + 384;         // 128

    const int t  = threadIdx.x;
    const int mb = blockIdx.x * 64;

    for (int i = t; i < 12288; i += TPB) sw[i] = w[i];
    for (int i = t; i < 384;   i += TPB) saff[i] = g_aff1[i];
    for (int i = t; i < 128;   i += TPB) sred[i] = 0.f;
    __syncthreads();

    // phase 1: y_cat = relu(a * (a>=0 ? max : min) + c), transposed into sy
    for (int i = t; i < 64*192; i += TPB) {
        const int mi = i / 192, q = i - mi*192;
        int m = mb + mi; if (m >= MPTS) m = MPTS - 1;
        const float a = saff[q], c = saff[192 + q];
        const float v = (a >= 0.f) ? g_Mx[(size_t)m*192 + q]
                                   : g_Mn[(size_t)m*192 + q];
        sy[q*66 + mi] = fmaxf(fmaf(a, v, c), 0.f);
    }
    __syncthreads();

    const int og = t & 7, mq = t >> 3;  // 8 o-groups x 32 m-groups
    const int o0 = og * 8;
    const int mi0 = mq * 2;

    unsigned long long acc[2][4];
    {
        const float4 b0 = *reinterpret_cast<const float4*>(bias + o0);
        const float4 b1 = *reinterpret_cast<const float4*>(bias + o0 + 4);
        acc[0][0] = pack2(b0.x, b0.y); acc[0][1] = pack2(b0.z, b0.w);
        acc[0][2] = pack2(b1.x, b1.y); acc[0][3] = pack2(b1.z, b1.w);
#pragma unroll
        for (int j = 0; j < 4; j++) acc[1][j] = acc[0][j];
    }
#pragma unroll 4
    for (int q = 0; q < 192; q++) {
        const float2 yv = *reinterpret_cast<const float2*>(&sy[q*66 + mi0]);
        const unsigned long long y0 = pack2(yv.x, yv.x);
        const unsigned long long y1 = pack2(yv.y, yv.y);
        const ulonglong2 wv  = *reinterpret_cast<const ulonglong2*>(sw + q*64 + o0);
        const ulonglong2 wv2 = *reinterpret_cast<const ulonglong2*>(sw + q*64 + o0 + 4);
        fma2(acc[0][0], y0, wv.x);  fma2(acc[0][1], y0, wv.y);
        fma2(acc[0][2], y0, wv2.x); fma2(acc[0][3], y0, wv2.y);
        fma2(acc[1][0], y1, wv.x);  fma2(acc[1][1], y1, wv.y);
        fma2(acc[1][2], y1, wv2.x); fma2(acc[1][3], y1, wv2.y);
    }
#pragma unroll
    for (int mm = 0; mm < 2; mm++) {
        const int m = mb + mi0 + mm;
        if (m < MPTS) {
            const float2 a0 = unpack2(acc[mm][0]), a1 = unpack2(acc[mm][1]);
            const float2 a2 = unpack2(acc[mm][2]), a3 = unpack2(acc[mm][3]);
            float* dst = g_zbuf + (size_t)m*64 + o0;
            *reinterpret_cast<float4*>(dst)     = make_float4(a0.x, a0.y, a1.x, a1.y);
            *reinterpret_cast<float4*>(dst + 4) = make_float4(a2.x, a2.y, a3.x, a3.y);
            const float vals[8] = {a0.x, a0.y, a1.x, a1.y, a2.x, a2.y, a3.x, a3.y};
#pragma unroll
            for (int k = 0; k < 8; k++) {
                atomicAdd(&sred[o0 + k], vals[k]);
                atomicAdd(&sred[64 + o0 + k], vals[k]*vals[k]);
            }
        }
    }
    __syncthreads();
    for (int i = t; i < 128; i += TPB)
        atomicAdd(&g_fsum[i], (double)sred[i]);
}

// ---------------- kernel 4: final BN affine params ------------------------
__global__ void k_stats2(const float* __restrict__ g, const float* __restrict__ be)
{
    const int o = threadIdx.x;
    if (o >= 64) return;
    const double cnt = (double)MPTS;
    const double mu  = g_fsum[o] / cnt;
    const double var = g_fsum[64 + o] / cnt - mu*mu;
    const double a = (double)g[o] / sqrt(var + 1e-5);
    g_aff2[o]      = (float)a;
    g_aff2[64 + o] = (float)((double)be[o] - mu*a);
}

// ---------------- kernel 5: final elementwise BN+relu + n_o ---------------
__global__ void k_final(float* __restrict__ out_y, float* __restrict__ out_no)
{
    const int i = blockIdx.x * blockDim.x + threadIdx.x;  // float4 groups
    if (i < MPTS*16) {
        const int o0 = (i & 15) * 4;
        const float4 z = *reinterpret_cast<const float4*>(&g_zbuf[(size_t)i*4]);
        float4 r;
        r.x = fmaxf(fmaf(g_aff2[o0+0], z.x, g_aff2[64+o0+0]), 0.f);
        r.y = fmaxf(fmaf(g_aff2[o0+1], z.y, g_aff2[64+o0+1]), 0.f);
        r.z = fmaxf(fmaf(g_aff2[o0+2], z.z, g_aff2[64+o0+2]), 0.f);
        r.w = fmaxf(fmaf(g_aff2[o0+3], z.w, g_aff2[64+o0+3]), 0.f);
        *reinterpret_cast<float4*>(&out_y[(size_t)i*4]) = r;
    }
    if (i == 0) out_no[0] = (float)MPTS;
}

// ---------------- launch ---------------------------------------------------
extern "C" void kernel_launch(void* const* d_in, const int* in_sizes, int n_in,
                              void* d_out, int out_size)
{
    const float* p   = (const float*)d_in[0];
    const float* x   = (const float*)d_in[1];
    const int*   fps = (const int*)  d_in[3];
    const int*   knn = (const int*)  d_in[4];
    const float* w1  = (const float*)d_in[5];
    const float* w2  = (const float*)d_in[6];
    const float* w3  = (const float*)d_in[7];
    const float* w   = (const float*)d_in[8];
    const float* b   = (const float*)d_in[9];
    const float* g1  = (const float*)d_in[10];
    const float* g2  = (const float*)d_in[11];
    const float* g3  = (const float*)d_in[12];
    const float* g   = (const float*)d_in[13];
    const float* be1 = (const float*)d_in[14];
    const float* be2 = (const float*)d_in[15];
    const float* be3 = (const float*)d_in[16];
    const float* be  = (const float*)d_in[17];

    float* out    = (float*)d_out;
    float* out_np = out;                                      // [M,3]
    float* out_y  = out + (size_t)MPTS*3;                     // [M,64]
    float* out_no = out + (size_t)MPTS*3 + (size_t)MPTS*64;   // [1]

    const int smemA = (8192*2 + 6144) * 4;                    // 90112
    const int smemG = (12288 + 12672 + 384 + 128) * 4;        // 101888
    cudaFuncSetAttribute(k_pgemm, cudaFuncAttributeMaxDynamicSharedMemorySize, smemA);
    cudaFuncSetAttribute(k_gemm2, cudaFuncAttributeMaxDynamicSharedMemorySize, smemG);

    k_init<<<1, 512>>>();
    k_pgemm<<<1875, TPB, smemA>>>(x, w1, w2, w3);
    k_comb<<<3750, TPB>>>(p, fps, knn, w1, w2, w3, out_np);
    k_stats1<<<1, 192>>>(g1, g2, g3, be1, be2, be3);
    k_gemm2<<<938, TPB, smemG>>>(w, b);
    k_stats2<<<1, 64>>>(g, be);
    k_final<<<3750, 256>>>(out_y, out_no);
}

// round 4
// speedup vs baseline: 1.3252x; 1.0405x over previous
#include <cuda_runtime.h>
#include <math.h>

#define NPTS 240000
#define MPTS 60000
#define TPB  256

typedef unsigned long long u64;

// ---------------- scratch (static device globals; no runtime alloc) -------
__device__ float  g_P[(size_t)NPTS*64];    // x-part for ONE branch (61MB, L2-hot)
__device__ float  g_Mx[(size_t)MPTS*192];  // per-m per-branch-channel max of h
__device__ float  g_Mn[(size_t)MPTS*192];  // min of h
__device__ float  g_zbuf[(size_t)MPTS*64]; // z = y_cat @ w + b
__device__ double g_bsum[384];             // [sum(192) | sumsq(192)] branch stats
__device__ double g_fsum[128];             // [sum(64)  | sumsq(64)]  final stats
__device__ float  g_aff1[384];             // [a(192) | c(192)]
__device__ float  g_aff2[128];             // [a(64)  | c(64)]

// ---------------- f32x2 helpers -------------------------------------------
__device__ __forceinline__ void fma2(u64 &d, u64 a, u64 b)
{
    asm("fma.rn.f32x2 %0, %1, %2, %0;" : "+l"(d) : "l"(a), "l"(b));
}
__device__ __forceinline__ void add2(u64 &d, u64 a)
{
    asm("add.rn.f32x2 %0, %0, %1;" : "+l"(d) : "l"(a));
}
__device__ __forceinline__ u64 pack2(float lo, float hi)
{
    u64 r;
    asm("mov.b64 %0, {%1, %2};" : "=l"(r) : "f"(lo), "f"(hi));
    return r;
}
__device__ __forceinline__ u64 dup2(float v)
{
    u64 r;
    asm("mov.b64 %0, {%1, %1};" : "=l"(r) : "f"(v));
    return r;
}
__device__ __forceinline__ float2 unpack2(u64 v)
{
    float2 r;
    asm("mov.b64 {%0, %1}, %2;" : "=f"(r.x), "=f"(r.y) : "l"(v));
    return r;
}

// ---------------- kernel 0: zero the stat accumulators --------------------
__global__ void k_init()
{
    int i = threadIdx.x;
    if (i < 384) g_bsum[i] = 0.0;
    if (i < 128) g_fsum[i] = 0.0;
}

// ---------------- kernel A: P[n,64] = x[n,:32] @ wb[3:35,:] (one branch) --
// 128 points per block (1875 blocks). og = t&7 (8 o of 8), ng = t>>3 (4 n).
__global__ void __launch_bounds__(TPB) k_pgemm(
    const float* __restrict__ x, const float* __restrict__ wb)
{
    extern __shared__ float smem[];
    float2* sxd = reinterpret_cast<float2*>(smem);  // [32 c][128 n] dup (32KB)
    float*  sw  = smem + 8192;                      // [32 c][64 o]   (8KB)

    const int t  = threadIdx.x;
    const int n0 = blockIdx.x * 128;

    for (int i = t; i < 2048; i += TPB) sw[i] = wb[192 + i];  // rows 3..34
    for (int i = t; i < 1024; i += TPB) {
        const int nl = i >> 3, c4 = i & 7;
        const float4 v = *reinterpret_cast<const float4*>(
            x + (size_t)(n0 + nl)*32 + c4*4);
        sxd[(c4*4 + 0)*128 + nl] = make_float2(v.x, v.x);
        sxd[(c4*4 + 1)*128 + nl] = make_float2(v.y, v.y);
        sxd[(c4*4 + 2)*128 + nl] = make_float2(v.z, v.z);
        sxd[(c4*4 + 3)*128 + nl] = make_float2(v.w, v.w);
    }
    __syncthreads();

    const int og = t & 7, ng = t >> 3;
    const int nb = ng * 4;
    const int o0 = og * 8;

    u64 acc[4][4];
#pragma unroll
    for (int i = 0; i < 4; i++)
#pragma unroll
        for (int j = 0; j < 4; j++) acc[i][j] = 0ULL;

#pragma unroll
    for (int c = 0; c < 32; c++) {
        const ulonglong2* xp = reinterpret_cast<const ulonglong2*>(sxd + c*128 + nb);
        const ulonglong2 xa = xp[0], xb = xp[1];
        const ulonglong2* wp = reinterpret_cast<const ulonglong2*>(sw + c*64 + o0);
        const ulonglong2 wv = wp[0], wv2 = wp[1];
        const u64 xv[4] = {xa.x, xa.y, xb.x, xb.y};
        const u64 wr[4] = {wv.x, wv.y, wv2.x, wv2.y};
#pragma unroll
        for (int i = 0; i < 4; i++)
#pragma unroll
            for (int j = 0; j < 4; j++) fma2(acc[i][j], xv[i], wr[j]);
    }
#pragma unroll
    for (int i = 0; i < 4; i++) {
        const int n = n0 + nb + i;
        const float2 a0 = unpack2(acc[i][0]), a1 = unpack2(acc[i][1]);
        const float2 a2 = unpack2(acc[i][2]), a3 = unpack2(acc[i][3]);
        float* dst = g_P + (size_t)n*64 + o0;
        *reinterpret_cast<float4*>(dst)     = make_float4(a0.x, a0.y, a1.x, a1.y);
        *reinterpret_cast<float4*>(dst + 4) = make_float4(a2.x, a2.y, a3.x, a3.y);
    }
}

// ---------------- kernel B: gather P (L2-hot) + rel + max/min + stats -----
// one branch per launch. 16 m per block (3750 blocks). og = t&15 (4 o each).
template<int KB>
__global__ void __launch_bounds__(TPB) k_comb(
    const float* __restrict__ p,
    const int* __restrict__ fps_idx, const int* __restrict__ knn_idx,
    const float* __restrict__ wb, float* __restrict__ out_np, int bidx)
{
    __shared__ float4 srel[16*KB];   // rel.xyz + P byte-offset
    __shared__ float  swx[192];      // xyz weight rows of this branch
    __shared__ float  scen[16*4];
    __shared__ float  sred[128];

    const int t  = threadIdx.x;
    const int mb = blockIdx.x * 16;

    if (t < 16) {
        const int fi = fps_idx[mb + t];
        scen[t*4+0] = p[fi*3+0];
        scen[t*4+1] = p[fi*3+1];
        scen[t*4+2] = p[fi*3+2];
    }
    for (int i = t; i < 192; i += TPB) swx[i] = wb[i];
    for (int i = t; i < 128; i += TPB) sred[i] = 0.f;
    __syncthreads();

    if (bidx == 0 && t < 48) {
        const int ml = t / 3, comp = t - ml*3;
        out_np[(mb + ml)*3 + comp] = scen[ml*4 + comp];
    }

    for (int s = t; s < 16*KB; s += TPB) {
        const int ml = s / KB, j = s - ml*KB;
        const int idx = knn_idx[(mb + ml)*40 + j];
        float4 r;
        r.x = p[idx*3+0] - scen[ml*4+0];
        r.y = p[idx*3+1] - scen[ml*4+1];
        r.z = p[idx*3+2] - scen[ml*4+2];
        r.w = __int_as_float(idx * 256);    // byte offset of P row
        srel[s] = r;
    }
    __syncthreads();

    const int ml = t >> 4, og = t & 15;
    const int m  = mb + ml;
    const char* Pbase = reinterpret_cast<const char*>(g_P);
    const u64* swx2 = reinterpret_cast<const u64*>(swx);

    const u64 wx01 = swx2[og*2],      wx23 = swx2[og*2 + 1];
    const u64 wy01 = swx2[32 + og*2], wy23 = swx2[32 + og*2 + 1];
    const u64 wz01 = swx2[64 + og*2], wz23 = swx2[64 + og*2 + 1];

    float mx0=-3e38f, mx1=-3e38f, mx2=-3e38f, mx3=-3e38f;
    float mn0= 3e38f, mn1= 3e38f, mn2= 3e38f, mn3= 3e38f;
    u64 smA = 0ULL, smB = 0ULL, sqA = 0ULL, sqB = 0ULL;

#pragma unroll 4
    for (int j = 0; j < KB; j++) {
        const float4 r = srel[ml*KB + j];
        const ulonglong2 P2 = *reinterpret_cast<const ulonglong2*>(
            Pbase + __float_as_int(r.w) + og*16);
        const u64 xx = dup2(r.x), yy = dup2(r.y), zz = dup2(r.z);
        u64 hA = P2.x, hB = P2.y;
        fma2(hA, xx, wx01); fma2(hB, xx, wx23);
        fma2(hA, yy, wy01); fma2(hB, yy, wy23);
        fma2(hA, zz, wz01); fma2(hB, zz, wz23);
        const float2 h01 = unpack2(hA), h23 = unpack2(hB);
        mx0 = fmaxf(mx0, h01.x); mx1 = fmaxf(mx1, h01.y);
        mx2 = fmaxf(mx2, h23.x); mx3 = fmaxf(mx3, h23.y);
        mn0 = fminf(mn0, h01.x); mn1 = fminf(mn1, h01.y);
        mn2 = fminf(mn2, h23.x); mn3 = fminf(mn3, h23.y);
        add2(smA, hA); add2(smB, hB);
        fma2(sqA, hA, hA); fma2(sqB, hB, hB);
    }

    const int o0 = og * 4;
    *reinterpret_cast<float4*>(&g_Mx[(size_t)m*192 + bidx*64 + o0]) =
        make_float4(mx0, mx1, mx2, mx3);
    *reinterpret_cast<float4*>(&g_Mn[(size_t)m*192 + bidx*64 + o0]) =
        make_float4(mn0, mn1, mn2, mn3);

    const float2 s01 = unpack2(smA), s23 = unpack2(smB);
    const float2 q01 = unpack2(sqA), q23 = unpack2(sqB);
    atomicAdd(&sred[o0 + 0], s01.x);
    atomicAdd(&sred[o0 + 1], s01.y);
    atomicAdd(&sred[o0 + 2], s23.x);
    atomicAdd(&sred[o0 + 3], s23.y);
    atomicAdd(&sred[64 + o0 + 0], q01.x);
    atomicAdd(&sred[64 + o0 + 1], q01.y);
    atomicAdd(&sred[64 + o0 + 2], q23.x);
    atomicAdd(&sred[64 + o0 + 3], q23.y);

    __syncthreads();
    for (int i = t; i < 64; i += TPB) {
        atomicAdd(&g_bsum[bidx*64 + i], (double)sred[i]);
        atomicAdd(&g_bsum[192 + bidx*64 + i], (double)sred[64 + i]);
    }
}

// ---------------- kernel 2: branch BN affine params -----------------------
__global__ void k_stats1(const float* __restrict__ g1, const float* __restrict__ g2,
                         const float* __restrict__ g3, const float* __restrict__ be1,
                         const float* __restrict__ be2, const float* __restrict__ be3)
{
    const int i = threadIdx.x;
    if (i >= 192) return;
    const int b = i / 64, o = i - b*64;
    const double cnt = (double)MPTS * ((b == 0) ? 10.0 : ((b == 1) ? 20.0 : 40.0));
    const double mu  = g_bsum[i] / cnt;
    const double var = g_bsum[192 + i] / cnt - mu*mu;
    const float gam = ((b == 0) ? g1 : ((b == 1) ? g2 : g3))[o];
    const float bet = ((b == 0) ? be1 : ((b == 1) ? be2 : be3))[o];
    const double a = (double)gam / sqrt(var + 1e-5);
    g_aff1[i]       = (float)a;
    g_aff1[192 + i] = (float)((double)bet - mu*a);
}

// ---------------- kernel 3: BN+relu on max/min, 192->64 GEMM, final stats -
__global__ void __launch_bounds__(TPB) k_gemm2(const float* __restrict__ w,
                                               const float* __restrict__ bias)
{
    extern __shared__ float smem[];
    float* sw   = smem;               // 12288  [192 q][64 o]
    float* sy   = sw + 12288;         // 12672  [192 q][66] (pad 2, m fastest)
    float* saff = sy + 12672;         // 384
    float* sred = saff + 384;         // 128

    const int t  = threadIdx.x;
    const int mb = blockIdx.x * 64;

    for (int i = t; i < 12288; i += TPB) sw[i] = w[i];
    for (int i = t; i < 384;   i += TPB) saff[i] = g_aff1[i];
    for (int i = t; i < 128;   i += TPB) sred[i] = 0.f;
    __syncthreads();

    for (int i = t; i < 64*192; i += TPB) {
        const int mi = i / 192, q = i - mi*192;
        int m = mb + mi; if (m >= MPTS) m = MPTS - 1;
        const float a = saff[q], c = saff[192 + q];
        const float v = (a >= 0.f) ? g_Mx[(size_t)m*192 + q]
                                   : g_Mn[(size_t)m*192 + q];
        sy[q*66 + mi] = fmaxf(fmaf(a, v, c), 0.f);
    }
    __syncthreads();

    const int og = t & 7, mq = t >> 3;
    const int o0 = og * 8;
    const int mi0 = mq * 2;

    u64 acc[2][4];
    {
        const float4 b0 = *reinterpret_cast<const float4*>(bias + o0);
        const float4 b1 = *reinterpret_cast<const float4*>(bias + o0 + 4);
        acc[0][0] = pack2(b0.x, b0.y); acc[0][1] = pack2(b0.z, b0.w);
        acc[0][2] = pack2(b1.x, b1.y); acc[0][3] = pack2(b1.z, b1.w);
#pragma unroll
        for (int j = 0; j < 4; j++) acc[1][j] = acc[0][j];
    }
#pragma unroll 4
    for (int q = 0; q < 192; q++) {
        const float2 yv = *reinterpret_cast<const float2*>(&sy[q*66 + mi0]);
        const u64 y0 = dup2(yv.x);
        const u64 y1 = dup2(yv.y);
        const ulonglong2 wv  = *reinterpret_cast<const ulonglong2*>(sw + q*64 + o0);
        const ulonglong2 wv2 = *reinterpret_cast<const ulonglong2*>(sw + q*64 + o0 + 4);
        fma2(acc[0][0], y0, wv.x);  fma2(acc[0][1], y0, wv.y);
        fma2(acc[0][2], y0, wv2.x); fma2(acc[0][3], y0, wv2.y);
        fma2(acc[1][0], y1, wv.x);  fma2(acc[1][1], y1, wv.y);
        fma2(acc[1][2], y1, wv2.x); fma2(acc[1][3], y1, wv2.y);
    }
#pragma unroll
    for (int mm = 0; mm < 2; mm++) {
        const int m = mb + mi0 + mm;
        if (m < MPTS) {
            const float2 a0 = unpack2(acc[mm][0]), a1 = unpack2(acc[mm][1]);
            const float2 a2 = unpack2(acc[mm][2]), a3 = unpack2(acc[mm][3]);
            float* dst = g_zbuf + (size_t)m*64 + o0;
            *reinterpret_cast<float4*>(dst)     = make_float4(a0.x, a0.y, a1.x, a1.y);
            *reinterpret_cast<float4*>(dst + 4) = make_float4(a2.x, a2.y, a3.x, a3.y);
            const float vals[8] = {a0.x, a0.y, a1.x, a1.y, a2.x, a2.y, a3.x, a3.y};
#pragma unroll
            for (int k = 0; k < 8; k++) {
                atomicAdd(&sred[o0 + k], vals[k]);
                atomicAdd(&sred[64 + o0 + k], vals[k]*vals[k]);
            }
        }
    }
    __syncthreads();
    for (int i = t; i < 128; i += TPB)
        atomicAdd(&g_fsum[i], (double)sred[i]);
}

// ---------------- kernel 4: final BN affine params ------------------------
__global__ void k_stats2(const float* __restrict__ g, const float* __restrict__ be)
{
    const int o = threadIdx.x;
    if (o >= 64) return;
    const double cnt = (double)MPTS;
    const double mu  = g_fsum[o] / cnt;
    const double var = g_fsum[64 + o] / cnt - mu*mu;
    const double a = (double)g[o] / sqrt(var + 1e-5);
    g_aff2[o]      = (float)a;
    g_aff2[64 + o] = (float)((double)be[o] - mu*a);
}

// ---------------- kernel 5: final elementwise BN+relu + n_o ---------------
__global__ void k_final(float* __restrict__ out_y, float* __restrict__ out_no)
{
    const int i = blockIdx.x * blockDim.x + threadIdx.x;
    if (i < MPTS*16) {
        const int o0 = (i & 15) * 4;
        const float4 z = *reinterpret_cast<const float4*>(&g_zbuf[(size_t)i*4]);
        float4 r;
        r.x = fmaxf(fmaf(g_aff2[o0+0], z.x, g_aff2[64+o0+0]), 0.f);
        r.y = fmaxf(fmaf(g_aff2[o0+1], z.y, g_aff2[64+o0+1]), 0.f);
        r.z = fmaxf(fmaf(g_aff2[o0+2], z.z, g_aff2[64+o0+2]), 0.f);
        r.w = fmaxf(fmaf(g_aff2[o0+3], z.w, g_aff2[64+o0+3]), 0.f);
        *reinterpret_cast<float4*>(&out_y[(size_t)i*4]) = r;
    }
    if (i == 0) out_no[0] = (float)MPTS;
}

// ---------------- launch ---------------------------------------------------
extern "C" void kernel_launch(void* const* d_in, const int* in_sizes, int n_in,
                              void* d_out, int out_size)
{
    const float* p   = (const float*)d_in[0];
    const float* x   = (const float*)d_in[1];
    const int*   fps = (const int*)  d_in[3];
    const int*   knn = (const int*)  d_in[4];
    const float* w1  = (const float*)d_in[5];
    const float* w2  = (const float*)d_in[6];
    const float* w3  = (const float*)d_in[7];
    const float* w   = (const float*)d_in[8];
    const float* b   = (const float*)d_in[9];
    const float* g1  = (const float*)d_in[10];
    const float* g2  = (const float*)d_in[11];
    const float* g3  = (const float*)d_in[12];
    const float* g   = (const float*)d_in[13];
    const float* be1 = (const float*)d_in[14];
    const float* be2 = (const float*)d_in[15];
    const float* be3 = (const float*)d_in[16];
    const float* be  = (const float*)d_in[17];

    float* out    = (float*)d_out;
    float* out_np = out;                                      // [M,3]
    float* out_y  = out + (size_t)MPTS*3;                     // [M,64]
    float* out_no = out + (size_t)MPTS*3 + (size_t)MPTS*64;   // [1]

    const int smemA = (8192*2 + 2048) * 4;                    // 40960
    const int smemG = (12288 + 12672 + 384 + 128) * 4;        // 101888
    cudaFuncSetAttribute(k_pgemm, cudaFuncAttributeMaxDynamicSharedMemorySize, smemA);
    cudaFuncSetAttribute(k_gemm2, cudaFuncAttributeMaxDynamicSharedMemorySize, smemG);

    k_init<<<1, 512>>>();

    // branch pipeline: produce P_b (61MB, stays in L2), consume immediately
    k_pgemm<<<1875, TPB, smemA>>>(x, w1);
    k_comb<10><<<3750, TPB>>>(p, fps, knn, w1, out_np, 0);
    k_pgemm<<<1875, TPB, smemA>>>(x, w2);
    k_comb<20><<<3750, TPB>>>(p, fps, knn, w2, out_np, 1);
    k_pgemm<<<1875, TPB, smemA>>>(x, w3);
    k_comb<40><<<3750, TPB>>>(p, fps, knn, w3, out_np, 2);

    k_stats1<<<1, 192>>>(g1, g2, g3, be1, be2, be3);
    k_gemm2<<<938, TPB, smemG>>>(w, b);
    k_stats2<<<1, 64>>>(g, be);
    k_final<<<3750, 256>>>(out_y, out_no);
}

// round 5
// speedup vs baseline: 1.3566x; 1.0237x over previous
#include <cuda_runtime.h>
#include <math.h>

#define NPTS 240000
#define MPTS 60000
#define TPB  256

typedef unsigned long long u64;

// ---------------- scratch (static device globals; no runtime alloc) -------
__device__ float  g_P[(size_t)NPTS*64];    // x-part for ONE branch (61MB, L2-hot)
__device__ float  g_Mx[(size_t)MPTS*192];  // per-m per-branch-channel max of h
__device__ float  g_Mn[(size_t)MPTS*192];  // min of h
__device__ float  g_zbuf[(size_t)MPTS*64]; // z = y_cat @ w + b
__device__ double g_bsum[8][384];          // mirrors: [sum(192)|sumsq(192)]
__device__ double g_fsum[8][128];          // mirrors: [sum(64)|sumsq(64)]

// ---------------- f32x2 helpers -------------------------------------------
__device__ __forceinline__ void fma2(u64 &d, u64 a, u64 b)
{
    asm("fma.rn.f32x2 %0, %1, %2, %0;" : "+l"(d) : "l"(a), "l"(b));
}
__device__ __forceinline__ void add2(u64 &d, u64 a)
{
    asm("add.rn.f32x2 %0, %0, %1;" : "+l"(d) : "l"(a));
}
__device__ __forceinline__ u64 pack2(float lo, float hi)
{
    u64 r;
    asm("mov.b64 %0, {%1, %2};" : "=l"(r) : "f"(lo), "f"(hi));
    return r;
}
__device__ __forceinline__ u64 dup2(float v)
{
    u64 r;
    asm("mov.b64 %0, {%1, %1};" : "=l"(r) : "f"(v));
    return r;
}
__device__ __forceinline__ float2 unpack2(u64 v)
{
    float2 r;
    asm("mov.b64 {%0, %1}, %2;" : "=f"(r.x), "=f"(r.y) : "l"(v));
    return r;
}

// ---------------- kernel A: P[n,64] = x[n,:32] @ wb[3:35,:] (one branch) --
// persistent: 592 blocks (=148*4, all resident), each loops tiles of 128 n.
// thread = og (t&7, 8 o) x ng (t>>3, 4 n). x staged [n][c] pad 34.
#define PG_GRID 592
#define PG_TILES 1875
__global__ void __launch_bounds__(TPB) k_pgemm(
    const float* __restrict__ x, const float* __restrict__ wb, int zero)
{
    extern __shared__ float smem[];
    float* sxn = smem;            // [128 n][34] pad  (4352 floats, 17KB)
    float* sw  = smem + 4352;     // [32 c][64 o]     (2048 floats,  8KB)

    const int t = threadIdx.x;

    if (zero && blockIdx.x == 0) {
        double* bs = &g_bsum[0][0];
        for (int i = t; i < 8*384; i += TPB) bs[i] = 0.0;
        double* fs = &g_fsum[0][0];
        for (int i = t; i < 8*128; i += TPB) fs[i] = 0.0;
    }

    for (int i = t; i < 2048; i += TPB) sw[i] = wb[192 + i];  // rows 3..34

    const int og = t & 7, ng = t >> 3;
    const int nb = ng * 4;
    const int o0 = og * 8;

    for (int tile = blockIdx.x; tile < PG_TILES; tile += PG_GRID) {
        const int n0 = tile * 128;
        __syncthreads();   // sxn reuse safe (and w ready on first iter)

        // stage x natural [n][c], conflict-free STS
        {
            const int nl = t >> 3, c4 = t & 7;
            const float4 v0 = *reinterpret_cast<const float4*>(
                x + (size_t)(n0 + nl)*32 + c4*4);
            const float4 v1 = *reinterpret_cast<const float4*>(
                x + (size_t)(n0 + 32 + nl)*32 + c4*4);
            const float4 v2 = *reinterpret_cast<const float4*>(
                x + (size_t)(n0 + 64 + nl)*32 + c4*4);
            const float4 v3 = *reinterpret_cast<const float4*>(
                x + (size_t)(n0 + 96 + nl)*32 + c4*4);
            float2* d0 = reinterpret_cast<float2*>(sxn + nl*34 + c4*4);
            float2* d1 = reinterpret_cast<float2*>(sxn + (nl+32)*34 + c4*4);
            float2* d2 = reinterpret_cast<float2*>(sxn + (nl+64)*34 + c4*4);
            float2* d3 = reinterpret_cast<float2*>(sxn + (nl+96)*34 + c4*4);
            d0[0] = make_float2(v0.x, v0.y); d0[1] = make_float2(v0.z, v0.w);
            d1[0] = make_float2(v1.x, v1.y); d1[1] = make_float2(v1.z, v1.w);
            d2[0] = make_float2(v2.x, v2.y); d2[1] = make_float2(v2.z, v2.w);
            d3[0] = make_float2(v3.x, v3.y); d3[1] = make_float2(v3.z, v3.w);
        }
        __syncthreads();

        u64 acc[4][4];
#pragma unroll
        for (int i = 0; i < 4; i++)
#pragma unroll
            for (int j = 0; j < 4; j++) acc[i][j] = 0ULL;

#pragma unroll
        for (int c = 0; c < 32; c++) {
            const u64 x0 = dup2(sxn[(nb+0)*34 + c]);
            const u64 x1 = dup2(sxn[(nb+1)*34 + c]);
            const u64 x2 = dup2(sxn[(nb+2)*34 + c]);
            const u64 x3 = dup2(sxn[(nb+3)*34 + c]);
            const ulonglong2 wv  = *reinterpret_cast<const ulonglong2*>(sw + c*64 + o0);
            const ulonglong2 wv2 = *reinterpret_cast<const ulonglong2*>(sw + c*64 + o0 + 4);
            const u64 xv[4] = {x0, x1, x2, x3};
            const u64 wr[4] = {wv.x, wv.y, wv2.x, wv2.y};
#pragma unroll
            for (int i = 0; i < 4; i++)
#pragma unroll
                for (int j = 0; j < 4; j++) fma2(acc[i][j], xv[i], wr[j]);
        }
#pragma unroll
        for (int i = 0; i < 4; i++) {
            const int n = n0 + nb + i;
            const float2 a0 = unpack2(acc[i][0]), a1 = unpack2(acc[i][1]);
            const float2 a2 = unpack2(acc[i][2]), a3 = unpack2(acc[i][3]);
            float* dst = g_P + (size_t)n*64 + o0;
            *reinterpret_cast<float4*>(dst)     = make_float4(a0.x, a0.y, a1.x, a1.y);
            *reinterpret_cast<float4*>(dst + 4) = make_float4(a2.x, a2.y, a3.x, a3.y);
        }
    }
}

// ---------------- kernel B: gather P (L2-hot) + rel + max/min + stats -----
// one branch per launch. 16 m per block (3750 blocks). og = t&15 (4 o each).
template<int KB>
__global__ void __launch_bounds__(TPB) k_comb(
    const float* __restrict__ p,
    const int* __restrict__ fps_idx, const int* __restrict__ knn_idx,
    const float* __restrict__ wb, float* __restrict__ out_np, int bidx)
{
    __shared__ float4 srel[16*KB];   // rel.xyz + P byte-offset
    __shared__ float  swx[192];      // xyz weight rows of this branch
    __shared__ float  scen[16*4];
    __shared__ float  sred[128];

    const int t  = threadIdx.x;
    const int mb = blockIdx.x * 16;

    if (t < 16) {
        const int fi = fps_idx[mb + t];
        scen[t*4+0] = p[fi*3+0];
        scen[t*4+1] = p[fi*3+1];
        scen[t*4+2] = p[fi*3+2];
    }
    for (int i = t; i < 192; i += TPB) swx[i] = wb[i];
    for (int i = t; i < 128; i += TPB) sred[i] = 0.f;
    __syncthreads();

    if (bidx == 0 && t < 48) {
        const int ml = t / 3, comp = t - ml*3;
        out_np[(mb + ml)*3 + comp] = scen[ml*4 + comp];
    }

    for (int s = t; s < 16*KB; s += TPB) {
        const int ml = s / KB, j = s - ml*KB;
        const int idx = knn_idx[(mb + ml)*40 + j];
        float4 r;
        r.x = p[idx*3+0] - scen[ml*4+0];
        r.y = p[idx*3+1] - scen[ml*4+1];
        r.z = p[idx*3+2] - scen[ml*4+2];
        r.w = __int_as_float(idx * 256);    // byte offset of P row
        srel[s] = r;
    }
    __syncthreads();

    const int ml = t >> 4, og = t & 15;
    const int m  = mb + ml;
    const char* Pbase = reinterpret_cast<const char*>(g_P);
    const u64* swx2 = reinterpret_cast<const u64*>(swx);

    const u64 wx01 = swx2[og*2],      wx23 = swx2[og*2 + 1];
    const u64 wy01 = swx2[32 + og*2], wy23 = swx2[32 + og*2 + 1];
    const u64 wz01 = swx2[64 + og*2], wz23 = swx2[64 + og*2 + 1];

    float mx0=-3e38f, mx1=-3e38f, mx2=-3e38f, mx3=-3e38f;
    float mn0= 3e38f, mn1= 3e38f, mn2= 3e38f, mn3= 3e38f;
    u64 smA = 0ULL, smB = 0ULL, sqA = 0ULL, sqB = 0ULL;

#pragma unroll 8
    for (int j = 0; j < KB; j++) {
        const float4 r = srel[ml*KB + j];
        const ulonglong2 P2 = *reinterpret_cast<const ulonglong2*>(
            Pbase + __float_as_int(r.w) + og*16);
        const u64 xx = dup2(r.x), yy = dup2(r.y), zz = dup2(r.z);
        u64 hA = P2.x, hB = P2.y;
        fma2(hA, xx, wx01); fma2(hB, xx, wx23);
        fma2(hA, yy, wy01); fma2(hB, yy, wy23);
        fma2(hA, zz, wz01); fma2(hB, zz, wz23);
        const float2 h01 = unpack2(hA), h23 = unpack2(hB);
        mx0 = fmaxf(mx0, h01.x); mx1 = fmaxf(mx1, h01.y);
        mx2 = fmaxf(mx2, h23.x); mx3 = fmaxf(mx3, h23.y);
        mn0 = fminf(mn0, h01.x); mn1 = fminf(mn1, h01.y);
        mn2 = fminf(mn2, h23.x); mn3 = fminf(mn3, h23.y);
        add2(smA, hA); add2(smB, hB);
        fma2(sqA, hA, hA); fma2(sqB, hB, hB);
    }

    const int o0 = og * 4;
    *reinterpret_cast<float4*>(&g_Mx[(size_t)m*192 + bidx*64 + o0]) =
        make_float4(mx0, mx1, mx2, mx3);
    *reinterpret_cast<float4*>(&g_Mn[(size_t)m*192 + bidx*64 + o0]) =
        make_float4(mn0, mn1, mn2, mn3);

    const float2 s01 = unpack2(smA), s23 = unpack2(smB);
    const float2 q01 = unpack2(sqA), q23 = unpack2(sqB);
    atomicAdd(&sred[o0 + 0], s01.x);
    atomicAdd(&sred[o0 + 1], s01.y);
    atomicAdd(&sred[o0 + 2], s23.x);
    atomicAdd(&sred[o0 + 3], s23.y);
    atomicAdd(&sred[64 + o0 + 0], q01.x);
    atomicAdd(&sred[64 + o0 + 1], q01.y);
    atomicAdd(&sred[64 + o0 + 2], q23.x);
    atomicAdd(&sred[64 + o0 + 3], q23.y);

    __syncthreads();
    const int mir = blockIdx.x & 7;
    for (int i = t; i < 64; i += TPB) {
        atomicAdd(&g_bsum[mir][bidx*64 + i], (double)sred[i]);
        atomicAdd(&g_bsum[mir][192 + bidx*64 + i], (double)sred[64 + i]);
    }
}

// ---------------- kernel 3: BN affine (inline) + 192->64 GEMM + stats -----
__global__ void __launch_bounds__(TPB) k_gemm2(
    const float* __restrict__ w, const float* __restrict__ bias,
    const float* __restrict__ g1, const float* __restrict__ g2,
    const float* __restrict__ g3, const float* __restrict__ be1,
    const float* __restrict__ be2, const float* __restrict__ be3)
{
    extern __shared__ float smem[];
    float* sw   = smem;               // 12288  [192 q][64 o]
    float* sy   = sw + 12288;         // 12672  [192 q][66] (pad 2, m fastest)
    float* saff = sy + 12672;         // 384
    float* sred = saff + 384;         // 128

    const int t  = threadIdx.x;
    const int mb = blockIdx.x * 64;

    for (int i = t; i < 12288; i += TPB) sw[i] = w[i];
    for (int i = t; i < 128;   i += TPB) sred[i] = 0.f;
    // branch BN affine from mirrored sums
    if (t < 192) {
        double s = 0.0, q = 0.0;
#pragma unroll
        for (int k = 0; k < 8; k++) { s += g_bsum[k][t]; q += g_bsum[k][192 + t]; }
        const int b = t / 64, o = t - b*64;
        const double cnt = (double)MPTS * ((b == 0) ? 10.0 : ((b == 1) ? 20.0 : 40.0));
        const double mu  = s / cnt;
        const double var = q / cnt - mu*mu;
        const float gam = ((b == 0) ? g1 : ((b == 1) ? g2 : g3))[o];
        const float bet = ((b == 0) ? be1 : ((b == 1) ? be2 : be3))[o];
        const double a = (double)gam / sqrt(var + 1e-5);
        saff[t]       = (float)a;
        saff[192 + t] = (float)((double)bet - mu*a);
    }
    __syncthreads();

    for (int i = t; i < 64*192; i += TPB) {
        const int mi = i / 192, q = i - mi*192;
        int m = mb + mi; if (m >= MPTS) m = MPTS - 1;
        const float a = saff[q], c = saff[192 + q];
        const float v = (a >= 0.f) ? g_Mx[(size_t)m*192 + q]
                                   : g_Mn[(size_t)m*192 + q];
        sy[q*66 + mi] = fmaxf(fmaf(a, v, c), 0.f);
    }
    __syncthreads();

    const int og = t & 7, mq = t >> 3;
    const int o0 = og * 8;
    const int mi0 = mq * 2;

    u64 acc[2][4];
    {
        const float4 b0 = *reinterpret_cast<const float4*>(bias + o0);
        const float4 b1 = *reinterpret_cast<const float4*>(bias + o0 + 4);
        acc[0][0] = pack2(b0.x, b0.y); acc[0][1] = pack2(b0.z, b0.w);
        acc[0][2] = pack2(b1.x, b1.y); acc[0][3] = pack2(b1.z, b1.w);
#pragma unroll
        for (int j = 0; j < 4; j++) acc[1][j] = acc[0][j];
    }
#pragma unroll 4
    for (int q = 0; q < 192; q++) {
        const float2 yv = *reinterpret_cast<const float2*>(&sy[q*66 + mi0]);
        const u64 y0 = dup2(yv.x);
        const u64 y1 = dup2(yv.y);
        const ulonglong2 wv  = *reinterpret_cast<const ulonglong2*>(sw + q*64 + o0);
        const ulonglong2 wv2 = *reinterpret_cast<const ulonglong2*>(sw + q*64 + o0 + 4);
        fma2(acc[0][0], y0, wv.x);  fma2(acc[0][1], y0, wv.y);
        fma2(acc[0][2], y0, wv2.x); fma2(acc[0][3], y0, wv2.y);
        fma2(acc[1][0], y1, wv.x);  fma2(acc[1][1], y1, wv.y);
        fma2(acc[1][2], y1, wv2.x); fma2(acc[1][3], y1, wv2.y);
    }
#pragma unroll
    for (int mm = 0; mm < 2; mm++) {
        const int m = mb + mi0 + mm;
        if (m < MPTS) {
            const float2 a0 = unpack2(acc[mm][0]), a1 = unpack2(acc[mm][1]);
            const float2 a2 = unpack2(acc[mm][2]), a3 = unpack2(acc[mm][3]);
            float* dst = g_zbuf + (size_t)m*64 + o0;
            *reinterpret_cast<float4*>(dst)     = make_float4(a0.x, a0.y, a1.x, a1.y);
            *reinterpret_cast<float4*>(dst + 4) = make_float4(a2.x, a2.y, a3.x, a3.y);
            const float vals[8] = {a0.x, a0.y, a1.x, a1.y, a2.x, a2.y, a3.x, a3.y};
#pragma unroll
            for (int k = 0; k < 8; k++) {
                atomicAdd(&sred[o0 + k], vals[k]);
                atomicAdd(&sred[64 + o0 + k], vals[k]*vals[k]);
            }
        }
    }
    __syncthreads();
    const int mir = blockIdx.x & 7;
    for (int i = t; i < 128; i += TPB)
        atomicAdd(&g_fsum[mir][i], (double)sred[i]);
}

// ---------------- kernel 5: final BN affine (inline) + relu + n_o ---------
__global__ void __launch_bounds__(TPB) k_final(
    const float* __restrict__ g, const float* __restrict__ be,
    float* __restrict__ out_y, float* __restrict__ out_no)
{
    __shared__ float aff[128];
    const int t = threadIdx.x;
    if (t < 64) {
        double s = 0.0, q = 0.0;
#pragma unroll
        for (int k = 0; k < 8; k++) { s += g_fsum[k][t]; q += g_fsum[k][64 + t]; }
        const double cnt = (double)MPTS;
        const double mu  = s / cnt;
        const double var = q / cnt - mu*mu;
        const double a = (double)g[t] / sqrt(var + 1e-5);
        aff[t]      = (float)a;
        aff[64 + t] = (float)((double)be[t] - mu*a);
    }
    __syncthreads();

    const int i = blockIdx.x * blockDim.x + t;   // float4 groups
    if (i < MPTS*16) {
        const int o0 = (i & 15) * 4;
        const float4 z = *reinterpret_cast<const float4*>(&g_zbuf[(size_t)i*4]);
        float4 r;
        r.x = fmaxf(fmaf(aff[o0+0], z.x, aff[64+o0+0]), 0.f);
        r.y = fmaxf(fmaf(aff[o0+1], z.y, aff[64+o0+1]), 0.f);
        r.z = fmaxf(fmaf(aff[o0+2], z.z, aff[64+o0+2]), 0.f);
        r.w = fmaxf(fmaf(aff[o0+3], z.w, aff[64+o0+3]), 0.f);
        *reinterpret_cast<float4*>(&out_y[(size_t)i*4]) = r;
    }
    if (i == 0) out_no[0] = (float)MPTS;
}

// ---------------- launch ---------------------------------------------------
extern "C" void kernel_launch(void* const* d_in, const int* in_sizes, int n_in,
                              void* d_out, int out_size)
{
    const float* p   = (const float*)d_in[0];
    const float* x   = (const float*)d_in[1];
    const int*   fps = (const int*)  d_in[3];
    const int*   knn = (const int*)  d_in[4];
    const float* w1  = (const float*)d_in[5];
    const float* w2  = (const float*)d_in[6];
    const float* w3  = (const float*)d_in[7];
    const float* w   = (const float*)d_in[8];
    const float* b   = (const float*)d_in[9];
    const float* g1  = (const float*)d_in[10];
    const float* g2  = (const float*)d_in[11];
    const float* g3  = (const float*)d_in[12];
    const float* g   = (const float*)d_in[13];
    const float* be1 = (const float*)d_in[14];
    const float* be2 = (const float*)d_in[15];
    const float* be3 = (const float*)d_in[16];
    const float* be  = (const float*)d_in[17];

    float* out    = (float*)d_out;
    float* out_np = out;                                      // [M,3]
    float* out_y  = out + (size_t)MPTS*3;                     // [M,64]
    float* out_no = out + (size_t)MPTS*3 + (size_t)MPTS*64;   // [1]

    const int smemA = (4352 + 2048) * 4;                      // 25600
    const int smemG = (12288 + 12672 + 384 + 128) * 4;        // 101888
    cudaFuncSetAttribute(k_pgemm, cudaFuncAttributeMaxDynamicSharedMemorySize, smemA);
    cudaFuncSetAttribute(k_gemm2, cudaFuncAttributeMaxDynamicSharedMemorySize, smemG);

    // branch pipeline: produce P_b (61MB, stays in L2), consume immediately
    k_pgemm<<<PG_GRID, TPB, smemA>>>(x, w1, 1);
    k_comb<10><<<3750, TPB>>>(p, fps, knn, w1, out_np, 0);
    k_pgemm<<<PG_GRID, TPB, smemA>>>(x, w2, 0);
    k_comb<20><<<3750, TPB>>>(p, fps, knn, w2, out_np, 1);
    k_pgemm<<<PG_GRID, TPB, smemA>>>(x, w3, 0);
    k_comb<40><<<3750, TPB>>>(p, fps, knn, w3, out_np, 2);

    k_gemm2<<<938, TPB, smemG>>>(w, b, g1, g2, g3, be1, be2, be3);
    k_final<<<3750, TPB>>>(g, be, out_y, out_no);
}

// round 6
// speedup vs baseline: 1.3862x; 1.0218x over previous
#include <cuda_runtime.h>
#include <math.h>

#define NPTS 240000
#define MPTS 60000
#define TPB  256

typedef unsigned long long u64;

// ---------------- scratch (static device globals; no runtime alloc) -------
__device__ float  g_P[(size_t)NPTS*64];    // x-part for ONE branch (61MB, L2-hot)
__device__ float  g_Mx[(size_t)MPTS*192];  // per-m per-branch-channel max of h
__device__ float  g_Mn[(size_t)MPTS*192];  // min of h
__device__ float  g_zbuf[(size_t)MPTS*64]; // z = y_cat @ w + b
__device__ double g_bsum[8][384];          // mirrors: [sum(192)|sumsq(192)]
__device__ double g_fsum[8][128];          // mirrors: [sum(64)|sumsq(64)]

// ---------------- f32x2 helpers -------------------------------------------
__device__ __forceinline__ void fma2(u64 &d, u64 a, u64 b)
{
    asm("fma.rn.f32x2 %0, %1, %2, %0;" : "+l"(d) : "l"(a), "l"(b));
}
__device__ __forceinline__ void add2(u64 &d, u64 a)
{
    asm("add.rn.f32x2 %0, %0, %1;" : "+l"(d) : "l"(a));
}
__device__ __forceinline__ u64 pack2(float lo, float hi)
{
    u64 r;
    asm("mov.b64 %0, {%1, %2};" : "=l"(r) : "f"(lo), "f"(hi));
    return r;
}
__device__ __forceinline__ u64 dup2(float v)
{
    u64 r;
    asm("mov.b64 %0, {%1, %1};" : "=l"(r) : "f"(v));
    return r;
}
__device__ __forceinline__ float2 unpack2(u64 v)
{
    float2 r;
    asm("mov.b64 {%0, %1}, %2;" : "=f"(r.x), "=f"(r.y) : "l"(v));
    return r;
}

// ---------------- kernel A: P[n,64] = x[n,:32] @ wb[3:35,:] (one branch) --
// persistent: 592 blocks (=148*4, all resident), each loops tiles of 128 n.
// thread = og (t&7, 8 o) x ng (t>>3, 4 n). x staged [n][c] pad 34.
#define PG_GRID 592
#define PG_TILES 1875
__global__ void __launch_bounds__(TPB) k_pgemm(
    const float* __restrict__ x, const float* __restrict__ wb, int zero)
{
    extern __shared__ float smem[];
    float* sxn = smem;            // [128 n][34] pad  (4352 floats, 17KB)
    float* sw  = smem + 4352;     // [32 c][64 o]     (2048 floats,  8KB)

    const int t = threadIdx.x;

    if (zero && blockIdx.x == 0) {
        double* bs = &g_bsum[0][0];
        for (int i = t; i < 8*384; i += TPB) bs[i] = 0.0;
        double* fs = &g_fsum[0][0];
        for (int i = t; i < 8*128; i += TPB) fs[i] = 0.0;
    }

    for (int i = t; i < 2048; i += TPB) sw[i] = wb[192 + i];  // rows 3..34

    const int og = t & 7, ng = t >> 3;
    const int nb = ng * 4;
    const int o0 = og * 8;

    for (int tile = blockIdx.x; tile < PG_TILES; tile += PG_GRID) {
        const int n0 = tile * 128;
        __syncthreads();   // sxn reuse safe (and w ready on first iter)

        // stage x natural [n][c], conflict-free STS
        {
            const int nl = t >> 3, c4 = t & 7;
            const float4 v0 = *reinterpret_cast<const float4*>(
                x + (size_t)(n0 + nl)*32 + c4*4);
            const float4 v1 = *reinterpret_cast<const float4*>(
                x + (size_t)(n0 + 32 + nl)*32 + c4*4);
            const float4 v2 = *reinterpret_cast<const float4*>(
                x + (size_t)(n0 + 64 + nl)*32 + c4*4);
            const float4 v3 = *reinterpret_cast<const float4*>(
                x + (size_t)(n0 + 96 + nl)*32 + c4*4);
            float2* d0 = reinterpret_cast<float2*>(sxn + nl*34 + c4*4);
            float2* d1 = reinterpret_cast<float2*>(sxn + (nl+32)*34 + c4*4);
            float2* d2 = reinterpret_cast<float2*>(sxn + (nl+64)*34 + c4*4);
            float2* d3 = reinterpret_cast<float2*>(sxn + (nl+96)*34 + c4*4);
            d0[0] = make_float2(v0.x, v0.y); d0[1] = make_float2(v0.z, v0.w);
            d1[0] = make_float2(v1.x, v1.y); d1[1] = make_float2(v1.z, v1.w);
            d2[0] = make_float2(v2.x, v2.y); d2[1] = make_float2(v2.z, v2.w);
            d3[0] = make_float2(v3.x, v3.y); d3[1] = make_float2(v3.z, v3.w);
        }
        __syncthreads();

        u64 acc[4][4];
#pragma unroll
        for (int i = 0; i < 4; i++)
#pragma unroll
            for (int j = 0; j < 4; j++) acc[i][j] = 0ULL;

#pragma unroll
        for (int c = 0; c < 32; c++) {
            const u64 x0 = dup2(sxn[(nb+0)*34 + c]);
            const u64 x1 = dup2(sxn[(nb+1)*34 + c]);
            const u64 x2 = dup2(sxn[(nb+2)*34 + c]);
            const u64 x3 = dup2(sxn[(nb+3)*34 + c]);
            const ulonglong2 wv  = *reinterpret_cast<const ulonglong2*>(sw + c*64 + o0);
            const ulonglong2 wv2 = *reinterpret_cast<const ulonglong2*>(sw + c*64 + o0 + 4);
            const u64 xv[4] = {x0, x1, x2, x3};
            const u64 wr[4] = {wv.x, wv.y, wv2.x, wv2.y};
#pragma unroll
            for (int i = 0; i < 4; i++)
#pragma unroll
                for (int j = 0; j < 4; j++) fma2(acc[i][j], xv[i], wr[j]);
        }
#pragma unroll
        for (int i = 0; i < 4; i++) {
            const int n = n0 + nb + i;
            const float2 a0 = unpack2(acc[i][0]), a1 = unpack2(acc[i][1]);
            const float2 a2 = unpack2(acc[i][2]), a3 = unpack2(acc[i][3]);
            float* dst = g_P + (size_t)n*64 + o0;
            *reinterpret_cast<float4*>(dst)     = make_float4(a0.x, a0.y, a1.x, a1.y);
            *reinterpret_cast<float4*>(dst + 4) = make_float4(a2.x, a2.y, a3.x, a3.y);
        }
    }
}

// ---------------- kernel B: gather P (L2-hot) + rel + max/min + stats -----
// one branch per launch. 8 m per block (7500 blocks), 1 warp per m.
// lane = og (0..15) x jh (0..1): j-split halves, combined via shfl_xor(1).
template<int KB>
__global__ void __launch_bounds__(TPB, 5) k_comb(
    const float* __restrict__ p,
    const int* __restrict__ fps_idx, const int* __restrict__ knn_idx,
    const float* __restrict__ wb, float* __restrict__ out_np, int bidx)
{
    __shared__ float4 srel[8*KB];    // rel.xyz + P byte-offset
    __shared__ float  swx[192];      // xyz weight rows of this branch
    __shared__ float  scen[8*4];
    __shared__ float  sred[128];

    const int t  = threadIdx.x;
    const int mb = blockIdx.x * 8;

    if (t < 8) {
        const int fi = fps_idx[mb + t];
        scen[t*4+0] = p[fi*3+0];
        scen[t*4+1] = p[fi*3+1];
        scen[t*4+2] = p[fi*3+2];
    }
    for (int i = t; i < 192; i += TPB) swx[i] = wb[i];
    for (int i = t; i < 128; i += TPB) sred[i] = 0.f;
    __syncthreads();

    if (bidx == 0 && t < 24) {
        const int ml = t / 3, comp = t - ml*3;
        out_np[(mb + ml)*3 + comp] = scen[ml*4 + comp];
    }

    for (int s = t; s < 8*KB; s += TPB) {
        const int ml = s / KB, j = s - ml*KB;
        const int idx = knn_idx[(mb + ml)*40 + j];
        float4 r;
        r.x = p[idx*3+0] - scen[ml*4+0];
        r.y = p[idx*3+1] - scen[ml*4+1];
        r.z = p[idx*3+2] - scen[ml*4+2];
        r.w = __int_as_float(idx * 256);    // byte offset of P row
        srel[s] = r;
    }
    __syncthreads();

    const int ml   = t >> 5;        // warp id = m within block
    const int lane = t & 31;
    const int og   = lane >> 1;     // 0..15
    const int jh   = lane & 1;      // j-half
    const int m    = mb + ml;
    const int JT   = KB / 2;
    const char* Pbase = reinterpret_cast<const char*>(g_P);
    const u64* swx2 = reinterpret_cast<const u64*>(swx);

    const u64 wx01 = swx2[og*2],      wx23 = swx2[og*2 + 1];
    const u64 wy01 = swx2[32 + og*2], wy23 = swx2[32 + og*2 + 1];
    const u64 wz01 = swx2[64 + og*2], wz23 = swx2[64 + og*2 + 1];

    float mx0=-3e38f, mx1=-3e38f, mx2=-3e38f, mx3=-3e38f;
    float mn0= 3e38f, mn1= 3e38f, mn2= 3e38f, mn3= 3e38f;
    u64 smA = 0ULL, smB = 0ULL, sqA = 0ULL, sqB = 0ULL;

    const float4* rbase = srel + ml*KB + jh*JT;
#pragma unroll
    for (int j = 0; j < JT; j++) {
        const float4 r = rbase[j];
        const ulonglong2 P2 = *reinterpret_cast<const ulonglong2*>(
            Pbase + __float_as_int(r.w) + og*16);
        const u64 xx = dup2(r.x), yy = dup2(r.y), zz = dup2(r.z);
        u64 hA = P2.x, hB = P2.y;
        fma2(hA, xx, wx01); fma2(hB, xx, wx23);
        fma2(hA, yy, wy01); fma2(hB, yy, wy23);
        fma2(hA, zz, wz01); fma2(hB, zz, wz23);
        const float2 h01 = unpack2(hA), h23 = unpack2(hB);
        mx0 = fmaxf(mx0, h01.x); mx1 = fmaxf(mx1, h01.y);
        mx2 = fmaxf(mx2, h23.x); mx3 = fmaxf(mx3, h23.y);
        mn0 = fminf(mn0, h01.x); mn1 = fminf(mn1, h01.y);
        mn2 = fminf(mn2, h23.x); mn3 = fminf(mn3, h23.y);
        add2(smA, hA); add2(smB, hB);
        fma2(sqA, hA, hA); fma2(sqB, hB, hB);
    }

    // combine the two j-halves (lane pairs differ only in jh)
    mx0 = fmaxf(mx0, __shfl_xor_sync(0xffffffffu, mx0, 1));
    mx1 = fmaxf(mx1, __shfl_xor_sync(0xffffffffu, mx1, 1));
    mx2 = fmaxf(mx2, __shfl_xor_sync(0xffffffffu, mx2, 1));
    mx3 = fmaxf(mx3, __shfl_xor_sync(0xffffffffu, mx3, 1));
    mn0 = fminf(mn0, __shfl_xor_sync(0xffffffffu, mn0, 1));
    mn1 = fminf(mn1, __shfl_xor_sync(0xffffffffu, mn1, 1));
    mn2 = fminf(mn2, __shfl_xor_sync(0xffffffffu, mn2, 1));
    mn3 = fminf(mn3, __shfl_xor_sync(0xffffffffu, mn3, 1));
    add2(smA, __shfl_xor_sync(0xffffffffu, smA, 1));
    add2(smB, __shfl_xor_sync(0xffffffffu, smB, 1));
    add2(sqA, __shfl_xor_sync(0xffffffffu, sqA, 1));
    add2(sqB, __shfl_xor_sync(0xffffffffu, sqB, 1));

    if (jh == 0) {
        const int o0 = og * 4;
        *reinterpret_cast<float4*>(&g_Mx[(size_t)m*192 + bidx*64 + o0]) =
            make_float4(mx0, mx1, mx2, mx3);
        *reinterpret_cast<float4*>(&g_Mn[(size_t)m*192 + bidx*64 + o0]) =
            make_float4(mn0, mn1, mn2, mn3);

        const float2 s01 = unpack2(smA), s23 = unpack2(smB);
        const float2 q01 = unpack2(sqA), q23 = unpack2(sqB);
        atomicAdd(&sred[o0 + 0], s01.x);
        atomicAdd(&sred[o0 + 1], s01.y);
        atomicAdd(&sred[o0 + 2], s23.x);
        atomicAdd(&sred[o0 + 3], s23.y);
        atomicAdd(&sred[64 + o0 + 0], q01.x);
        atomicAdd(&sred[64 + o0 + 1], q01.y);
        atomicAdd(&sred[64 + o0 + 2], q23.x);
        atomicAdd(&sred[64 + o0 + 3], q23.y);
    }

    __syncthreads();
    const int mir = blockIdx.x & 7;
    for (int i = t; i < 64; i += TPB) {
        atomicAdd(&g_bsum[mir][bidx*64 + i], (double)sred[i]);
        atomicAdd(&g_bsum[mir][192 + bidx*64 + i], (double)sred[64 + i]);
    }
}

// ---------------- kernel 3: BN affine (inline) + 192->64 GEMM + stats -----
__global__ void __launch_bounds__(TPB) k_gemm2(
    const float* __restrict__ w, const float* __restrict__ bias,
    const float* __restrict__ g1, const float* __restrict__ g2,
    const float* __restrict__ g3, const float* __restrict__ be1,
    const float* __restrict__ be2, const float* __restrict__ be3)
{
    extern __shared__ float smem[];
    float* sw   = smem;               // 12288  [192 q][64 o]
    float* sy   = sw + 12288;         // 12672  [192 q][66] (pad 2, m fastest)
    float* saff = sy + 12672;         // 384
    float* sred = saff + 384;         // 128

    const int t  = threadIdx.x;
    const int mb = blockIdx.x * 64;

    for (int i = t; i < 12288; i += TPB) sw[i] = w[i];
    for (int i = t; i < 128;   i += TPB) sred[i] = 0.f;
    // branch BN affine from mirrored sums
    if (t < 192) {
        double s = 0.0, q = 0.0;
#pragma unroll
        for (int k = 0; k < 8; k++) { s += g_bsum[k][t]; q += g_bsum[k][192 + t]; }
        const int b = t / 64, o = t - b*64;
        const double cnt = (double)MPTS * ((b == 0) ? 10.0 : ((b == 1) ? 20.0 : 40.0));
        const double mu  = s / cnt;
        const double var = q / cnt - mu*mu;
        const float gam = ((b == 0) ? g1 : ((b == 1) ? g2 : g3))[o];
        const float bet = ((b == 0) ? be1 : ((b == 1) ? be2 : be3))[o];
        const double a = (double)gam / sqrt(var + 1e-5);
        saff[t]       = (float)a;
        saff[192 + t] = (float)((double)bet - mu*a);
    }
    __syncthreads();

    for (int i = t; i < 64*192; i += TPB) {
        const int mi = i / 192, q = i - mi*192;
        int m = mb + mi; if (m >= MPTS) m = MPTS - 1;
        const float a = saff[q], c = saff[192 + q];
        const float v = (a >= 0.f) ? g_Mx[(size_t)m*192 + q]
                                   : g_Mn[(size_t)m*192 + q];
        sy[q*66 + mi] = fmaxf(fmaf(a, v, c), 0.f);
    }
    __syncthreads();

    const int og = t & 7, mq = t >> 3;
    const int o0 = og * 8;
    const int mi0 = mq * 2;

    u64 acc[2][4];
    {
        const float4 b0 = *reinterpret_cast<const float4*>(bias + o0);
        const float4 b1 = *reinterpret_cast<const float4*>(bias + o0 + 4);
        acc[0][0] = pack2(b0.x, b0.y); acc[0][1] = pack2(b0.z, b0.w);
        acc[0][2] = pack2(b1.x, b1.y); acc[0][3] = pack2(b1.z, b1.w);
#pragma unroll
        for (int j = 0; j < 4; j++) acc[1][j] = acc[0][j];
    }
#pragma unroll 4
    for (int q = 0; q < 192; q++) {
        const float2 yv = *reinterpret_cast<const float2*>(&sy[q*66 + mi0]);
        const u64 y0 = dup2(yv.x);
        const u64 y1 = dup2(yv.y);
        const ulonglong2 wv  = *reinterpret_cast<const ulonglong2*>(sw + q*64 + o0);
        const ulonglong2 wv2 = *reinterpret_cast<const ulonglong2*>(sw + q*64 + o0 + 4);
        fma2(acc[0][0], y0, wv.x);  fma2(acc[0][1], y0, wv.y);
        fma2(acc[0][2], y0, wv2.x); fma2(acc[0][3], y0, wv2.y);
        fma2(acc[1][0], y1, wv.x);  fma2(acc[1][1], y1, wv.y);
        fma2(acc[1][2], y1, wv2.x); fma2(acc[1][3], y1, wv2.y);
    }
#pragma unroll
    for (int mm = 0; mm < 2; mm++) {
        const int m = mb + mi0 + mm;
        if (m < MPTS) {
            const float2 a0 = unpack2(acc[mm][0]), a1 = unpack2(acc[mm][1]);
            const float2 a2 = unpack2(acc[mm][2]), a3 = unpack2(acc[mm][3]);
            float* dst = g_zbuf + (size_t)m*64 + o0;
            *reinterpret_cast<float4*>(dst)     = make_float4(a0.x, a0.y, a1.x, a1.y);
            *reinterpret_cast<float4*>(dst + 4) = make_float4(a2.x, a2.y, a3.x, a3.y);
            const float vals[8] = {a0.x, a0.y, a1.x, a1.y, a2.x, a2.y, a3.x, a3.y};
#pragma unroll
            for (int k = 0; k < 8; k++) {
                atomicAdd(&sred[o0 + k], vals[k]);
                atomicAdd(&sred[64 + o0 + k], vals[k]*vals[k]);
            }
        }
    }
    __syncthreads();
    const int mir = blockIdx.x & 7;
    for (int i = t; i < 128; i += TPB)
        atomicAdd(&g_fsum[mir][i], (double)sred[i]);
}

// ---------------- kernel 5: final BN affine (inline) + relu + n_o ---------
__global__ void __launch_bounds__(TPB) k_final(
    const float* __restrict__ g, const float* __restrict__ be,
    float* __restrict__ out_y, float* __restrict__ out_no)
{
    __shared__ float aff[128];
    const int t = threadIdx.x;
    if (t < 64) {
        double s = 0.0, q = 0.0;
#pragma unroll
        for (int k = 0; k < 8; k++) { s += g_fsum[k][t]; q += g_fsum[k][64 + t]; }
        const double cnt = (double)MPTS;
        const double mu  = s / cnt;
        const double var = q / cnt - mu*mu;
        const double a = (double)g[t] / sqrt(var + 1e-5);
        aff[t]      = (float)a;
        aff[64 + t] = (float)((double)be[t] - mu*a);
    }
    __syncthreads();

    const int i = blockIdx.x * blockDim.x + t;   // float4 groups
    if (i < MPTS*16) {
        const int o0 = (i & 15) * 4;
        const float4 z = *reinterpret_cast<const float4*>(&g_zbuf[(size_t)i*4]);
        float4 r;
        r.x = fmaxf(fmaf(aff[o0+0], z.x, aff[64+o0+0]), 0.f);
        r.y = fmaxf(fmaf(aff[o0+1], z.y, aff[64+o0+1]), 0.f);
        r.z = fmaxf(fmaf(aff[o0+2], z.z, aff[64+o0+2]), 0.f);
        r.w = fmaxf(fmaf(aff[o0+3], z.w, aff[64+o0+3]), 0.f);
        *reinterpret_cast<float4*>(&out_y[(size_t)i*4]) = r;
    }
    if (i == 0) out_no[0] = (float)MPTS;
}

// ---------------- launch ---------------------------------------------------
extern "C" void kernel_launch(void* const* d_in, const int* in_sizes, int n_in,
                              void* d_out, int out_size)
{
    const float* p   = (const float*)d_in[0];
    const float* x   = (const float*)d_in[1];
    const int*   fps = (const int*)  d_in[3];
    const int*   knn = (const int*)  d_in[4];
    const float* w1  = (const float*)d_in[5];
    const float* w2  = (const float*)d_in[6];
    const float* w3  = (const float*)d_in[7];
    const float* w   = (const float*)d_in[8];
    const float* b   = (const float*)d_in[9];
    const float* g1  = (const float*)d_in[10];
    const float* g2  = (const float*)d_in[11];
    const float* g3  = (const float*)d_in[12];
    const float* g   = (const float*)d_in[13];
    const float* be1 = (const float*)d_in[14];
    const float* be2 = (const float*)d_in[15];
    const float* be3 = (const float*)d_in[16];
    const float* be  = (const float*)d_in[17];

    float* out    = (float*)d_out;
    float* out_np = out;                                      // [M,3]
    float* out_y  = out + (size_t)MPTS*3;                     // [M,64]
    float* out_no = out + (size_t)MPTS*3 + (size_t)MPTS*64;   // [1]

    const int smemA = (4352 + 2048) * 4;                      // 25600
    const int smemG = (12288 + 12672 + 384 + 128) * 4;        // 101888
    cudaFuncSetAttribute(k_pgemm, cudaFuncAttributeMaxDynamicSharedMemorySize, smemA);
    cudaFuncSetAttribute(k_gemm2, cudaFuncAttributeMaxDynamicSharedMemorySize, smemG);

    // branch pipeline: produce P_b (61MB, stays in L2), consume immediately
    k_pgemm<<<PG_GRID, TPB, smemA>>>(x, w1, 1);
    k_comb<10><<<7500, TPB>>>(p, fps, knn, w1, out_np, 0);
    k_pgemm<<<PG_GRID, TPB, smemA>>>(x, w2, 0);
    k_comb<20><<<7500, TPB>>>(p, fps, knn, w2, out_np, 1);
    k_pgemm<<<PG_GRID, TPB, smemA>>>(x, w3, 0);
    k_comb<40><<<7500, TPB>>>(p, fps, knn, w3, out_np, 2);

    k_gemm2<<<938, TPB, smemG>>>(w, b, g1, g2, g3, be1, be2, be3);
    k_final<<<3750, TPB>>>(g, be, out_y, out_no);
}